// round 3
// baseline (speedup 1.0000x reference)
#include <cuda_runtime.h>
#include <cstdint>

// Geodesic rotation loss fwd+bwd, N=2,000,000 triples of 3x3 fp32 matrices.
//
// Inputs  (metadata order): d_in[0]=R_rel [N,3,3], d_in[1]=R_w2c1 [N,3,3], d_in[2]=R_w2c2 [N,3,3]
// Output  d_out (fp32, 1 + 9N + 9N):
//   [0]            loss (sum of arccos)
//   [1 .. 9N]      d_R_w2c1
//   [1+9N .. 18N]  d_R_w2c2
//
// Numerics: g = -0.5/sqrt(1-cos^2) amplifies a 1-ulp error in tr by
// ~1/theta^2 for small-angle samples; the norm error is dominated by the
// smallest-theta samples, so tr must match XLA's bit pattern:
//   - M = A^T * B2 : cuBLAS batched gemm K=3 -> ascending fused FFMA chain
//   - tr = <M, B1> : XLA fusion loop  -> UNFUSED mul + add, linear order
//   - denom = 1 - c*c : separate rounded mul and sub (no fma)
//   - g: correctly-rounded sqrt then divide

#define CLAMP_THR 0.9999999f

static constexpr int BLOCK  = 256;
static constexpr int N_MAX  = 2000000;
static constexpr int NBLK_MAX = (N_MAX + BLOCK - 1) / BLOCK;  // 7813

__device__ float g_partials[NBLK_MAX];

__global__ __launch_bounds__(BLOCK) void rotloss_kernel(
    const float* __restrict__ Rrel,
    const float* __restrict__ R1,
    const float* __restrict__ R2,
    float* __restrict__ d1,
    float* __restrict__ d2,
    int n)
{
    int idx = blockIdx.x * BLOCK + threadIdx.x;
    float local = 0.0f;

    if (idx < n) {
        size_t base = 9ull * (size_t)idx;
        float A[9], B1[9], B2[9];
        #pragma unroll
        for (int t = 0; t < 9; t++) {
            A[t]  = Rrel[base + t];
            B1[t] = R1[base + t];
            B2[t] = R2[base + t];
        }

        // M = A^T * B2 : M[i][k] = sum_j A[j][i] * B2[j][k]
        // cuBLAS-style ascending-K fused FFMA chain (first term == mul).
        float M[9];
        #pragma unroll
        for (int i = 0; i < 3; i++)
            #pragma unroll
            for (int k = 0; k < 3; k++) {
                float m = __fmul_rn(A[i], B2[k]);
                m = fmaf(A[3 + i], B2[3 + k], m);
                m = fmaf(A[6 + i], B2[6 + k], m);
                M[3 * i + k] = m;
            }

        // tr = <M, B1> : XLA fusion-loop style -> UNFUSED mul then add,
        // linear row-major order.
        float tr = __fmul_rn(M[0], B1[0]);
        #pragma unroll
        for (int t = 1; t < 9; t++)
            tr = __fadd_rn(tr, __fmul_rn(M[t], B1[t]));

        float cosv  = __fmul_rn(0.5f, __fsub_rn(tr, 1.0f));
        float cos_c = fminf(fmaxf(cosv, -CLAMP_THR), CLAMP_THR);
        local = acosf(cos_c);

        // denom = 1 - cos_c*cos_c : two separate rounded ops (NOT fma)
        float c2    = __fmul_rn(cos_c, cos_c);
        float denom = __fsub_rn(1.0f, c2);
        float g = 0.0f;
        if (fabsf(cosv) < CLAMP_THR) {
            g = __fdiv_rn(-0.5f, __fsqrt_rn(denom));
        }

        // d_R_w2c1 = g * M
        #pragma unroll
        for (int t = 0; t < 9; t++) d1[base + t] = __fmul_rn(g, M[t]);

        // d_R_w2c2 = g * (A * B1) : P[i][k] = sum_j A[i][j] * B1[j][k]
        // (also a cuBLAS K=3 batched gemm in the reference -> fused chain)
        #pragma unroll
        for (int i = 0; i < 3; i++)
            #pragma unroll
            for (int k = 0; k < 3; k++) {
                float p = __fmul_rn(A[3 * i], B1[k]);
                p = fmaf(A[3 * i + 1], B1[3 + k], p);
                p = fmaf(A[3 * i + 2], B1[6 + k], p);
                d2[base + 3 * i + k] = __fmul_rn(g, p);
            }
    }

    // Deterministic per-block reduction of the loss contribution.
    __shared__ float s[BLOCK];
    s[threadIdx.x] = local;
    __syncthreads();
    #pragma unroll
    for (int off = BLOCK / 2; off > 0; off >>= 1) {
        if (threadIdx.x < off) s[threadIdx.x] += s[threadIdx.x + off];
        __syncthreads();
    }
    if (threadIdx.x == 0) g_partials[blockIdx.x] = s[0];
}

__global__ __launch_bounds__(BLOCK) void reduce_kernel(int nblk, float* __restrict__ out)
{
    __shared__ float s[BLOCK];
    float local = 0.0f;
    for (int i = threadIdx.x; i < nblk; i += BLOCK) local += g_partials[i];
    s[threadIdx.x] = local;
    __syncthreads();
    #pragma unroll
    for (int off = BLOCK / 2; off > 0; off >>= 1) {
        if (threadIdx.x < off) s[threadIdx.x] += s[threadIdx.x + off];
        __syncthreads();
    }
    if (threadIdx.x == 0) out[0] = s[0];
}

extern "C" void kernel_launch(void* const* d_in, const int* in_sizes, int n_in,
                              void* d_out, int out_size)
{
    const float* Rrel = (const float*)d_in[0];
    const float* R1   = (const float*)d_in[1];
    const float* R2   = (const float*)d_in[2];
    float* out = (float*)d_out;

    int n = in_sizes[0] / 9;
    int nblk = (n + BLOCK - 1) / BLOCK;

    float* d1 = out + 1;
    float* d2 = out + 1 + 9ull * (size_t)n;

    rotloss_kernel<<<nblk, BLOCK>>>(Rrel, R1, R2, d1, d2, n);
    reduce_kernel<<<1, BLOCK>>>(nblk, out);
}

// round 4
// speedup vs baseline: 1.4483x; 1.4483x over previous
#include <cuda_runtime.h>
#include <cstdint>

// Geodesic rotation loss fwd+bwd, N=2,000,000 triples of 3x3 fp32 matrices.
//
// Inputs:  d_in[0]=R_rel [N,3,3], d_in[1]=R_w2c1 [N,3,3], d_in[2]=R_w2c2 [N,3,3]
// Output d_out (fp32, 1 + 9N + 9N): [0]=loss, [1..9N]=d_R_w2c1, [1+9N..18N]=d_R_w2c2
//
// R4: smem-staged coalesced float4 loads + coalesced scalar stores
// (9x fewer L1tex wavefronts than direct 36B-strided scalar access),
// single-kernel with last-block final reduction (deterministic fixed-order).
// Numerics identical to the passing R3 kernel — do not touch.

#define CLAMP_THR 0.9999999f

static constexpr int BLOCK = 256;           // threads == elements per block
static constexpr int N_MAX = 2000000;
static constexpr int NBLK_MAX = (N_MAX + BLOCK - 1) / BLOCK;  // 7813

__device__ float g_partials[NBLK_MAX];
__device__ unsigned int g_done_count = 0;   // self-resetting across graph replays

__global__ __launch_bounds__(BLOCK) void rotloss_kernel(
    const float* __restrict__ Rrel,
    const float* __restrict__ R1,
    const float* __restrict__ R2,
    float* __restrict__ out,   // out[0]=loss, d1=out+1, d2=out+1+9n
    int n, int nblk)
{
    __shared__ float sA [BLOCK * 9];
    __shared__ float sB1[BLOCK * 9];
    __shared__ float sB2[BLOCK * 9];
    __shared__ float sred[BLOCK];
    __shared__ bool  s_is_last;

    const int tid = threadIdx.x;
    const int e0  = blockIdx.x * BLOCK;
    const int cnt = min(BLOCK, n - e0);
    const int nf  = cnt * 9;                 // floats per staged array
    const size_t gbase = 9ull * (size_t)e0;  // float offset of this block's tile

    // ---- Coalesced staged loads (float4; gbase*4 bytes is 16B-aligned) ----
    {
        const float4* A4  = (const float4*)(Rrel + gbase);
        const float4* B14 = (const float4*)(R1   + gbase);
        const float4* B24 = (const float4*)(R2   + gbase);
        const int n4 = nf >> 2;
        for (int i = tid; i < n4; i += BLOCK) {
            ((float4*)sA )[i] = A4 [i];
            ((float4*)sB1)[i] = B14[i];
            ((float4*)sB2)[i] = B24[i];
        }
        for (int i = (n4 << 2) + tid; i < nf; i += BLOCK) {   // scalar remainder
            sA [i] = Rrel[gbase + i];
            sB1[i] = R1  [gbase + i];
            sB2[i] = R2  [gbase + i];
        }
    }
    __syncthreads();

    // ---- Per-element compute (registers) ----
    float local = 0.0f;
    float M[9], P[9];
    float g = 0.0f;
    const bool act = (tid < cnt);

    if (act) {
        float A[9], B1[9], B2[9];
        #pragma unroll
        for (int t = 0; t < 9; t++) {
            A[t]  = sA [9 * tid + t];
            B1[t] = sB1[9 * tid + t];
            B2[t] = sB2[9 * tid + t];
        }

        // M = A^T * B2 (ascending-K fused FFMA chain, first term = mul)
        #pragma unroll
        for (int i = 0; i < 3; i++)
            #pragma unroll
            for (int k = 0; k < 3; k++) {
                float m = __fmul_rn(A[i], B2[k]);
                m = fmaf(A[3 + i], B2[3 + k], m);
                m = fmaf(A[6 + i], B2[6 + k], m);
                M[3 * i + k] = m;
            }

        // tr = <M, B1> : UNFUSED mul + add, linear order (matches XLA fusion)
        float tr = __fmul_rn(M[0], B1[0]);
        #pragma unroll
        for (int t = 1; t < 9; t++)
            tr = __fadd_rn(tr, __fmul_rn(M[t], B1[t]));

        float cosv  = __fmul_rn(0.5f, __fsub_rn(tr, 1.0f));
        float cos_c = fminf(fmaxf(cosv, -CLAMP_THR), CLAMP_THR);
        local = acosf(cos_c);

        // denom = 1 - c*c : separate rounded ops (NOT fma); exact sqrt + div
        float c2    = __fmul_rn(cos_c, cos_c);
        float denom = __fsub_rn(1.0f, c2);
        if (fabsf(cosv) < CLAMP_THR)
            g = __fdiv_rn(-0.5f, __fsqrt_rn(denom));

        // P = A * B1 (fused chain)
        #pragma unroll
        for (int i = 0; i < 3; i++)
            #pragma unroll
            for (int k = 0; k < 3; k++) {
                float p = __fmul_rn(A[3 * i], B1[k]);
                p = fmaf(A[3 * i + 1], B1[3 + k], p);
                p = fmaf(A[3 * i + 2], B1[6 + k], p);
                P[3 * i + k] = p;
            }
    }
    __syncthreads();   // done reading input stages; reuse sA/sB1 for outputs

    if (act) {
        #pragma unroll
        for (int t = 0; t < 9; t++) {
            sA [9 * tid + t] = __fmul_rn(g, M[t]);
            sB1[9 * tid + t] = __fmul_rn(g, P[t]);
        }
    }
    __syncthreads();

    // ---- Coalesced scalar stores (d1/d2 are 4B-offset -> no float4) ----
    {
        float* __restrict__ d1 = out + 1;
        float* __restrict__ d2 = out + 1 + 9ull * (size_t)n;
        for (int i = tid; i < nf; i += BLOCK) {
            d1[gbase + i] = sA [i];
            d2[gbase + i] = sB1[i];
        }
    }

    // ---- Deterministic per-block loss reduction ----
    sred[tid] = local;
    __syncthreads();
    #pragma unroll
    for (int off = BLOCK / 2; off > 0; off >>= 1) {
        if (tid < off) sred[tid] += sred[tid + off];
        __syncthreads();
    }
    if (tid == 0) {
        g_partials[blockIdx.x] = sred[0];
        __threadfence();
        unsigned int prev = atomicAdd(&g_done_count, 1u);
        s_is_last = (prev == (unsigned int)(nblk - 1));
    }
    __syncthreads();

    // ---- Last block: fixed-order final reduce (deterministic) ----
    if (s_is_last) {
        float acc = 0.0f;
        for (int i = tid; i < nblk; i += BLOCK) acc += g_partials[i];
        sred[tid] = acc;
        __syncthreads();
        #pragma unroll
        for (int off = BLOCK / 2; off > 0; off >>= 1) {
            if (tid < off) sred[tid] += sred[tid + off];
            __syncthreads();
        }
        if (tid == 0) {
            out[0] = sred[0];
            g_done_count = 0;   // reset for next graph replay
        }
    }
}

extern "C" void kernel_launch(void* const* d_in, const int* in_sizes, int n_in,
                              void* d_out, int out_size)
{
    const float* Rrel = (const float*)d_in[0];
    const float* R1   = (const float*)d_in[1];
    const float* R2   = (const float*)d_in[2];
    float* out = (float*)d_out;

    int n = in_sizes[0] / 9;
    int nblk = (n + BLOCK - 1) / BLOCK;

    rotloss_kernel<<<nblk, BLOCK>>>(Rrel, R1, R2, out, n, nblk);
}

// round 9
// speedup vs baseline: 1.6473x; 1.1375x over previous
#include <cuda_runtime.h>
#include <cstdint>

// Geodesic rotation loss fwd+bwd, N=2,000,000 triples of 3x3 fp32 matrices.
//
// Inputs:  d_in[0]=R_rel [N,3,3], d_in[1]=R_w2c1 [N,3,3], d_in[2]=R_w2c2 [N,3,3]
// Output d_out (fp32, 1 + 9N + 9N): [0]=loss, [1..9N]=d_R_w2c1, [1+9N..18N]=d_R_w2c2
//
// R9 = resubmit of R7/R8 (two broker timeouts; kernel never ran).
// R7 = R5 with the d2 smem index typo fixed (sB1[9*tid + 3*i + k]).
//   - outputs written into each thread's PRIVATE smem slice immediately
//     (no barrier needed: slice is read only by its owner) -> fewer regs
//   - __launch_bounds__(256,5): 5 CTAs/SM
//   - warp-shuffle loss reduction
//   - __stcs streaming stores
// Numerics identical to the passing R3/R4 kernels — do not touch.

#define CLAMP_THR 0.9999999f

static constexpr int BLOCK = 256;
static constexpr int N_MAX = 2000000;
static constexpr int NBLK_MAX = (N_MAX + BLOCK - 1) / BLOCK;  // 7813

__device__ float g_partials[NBLK_MAX];
__device__ unsigned int g_done_count = 0;   // self-resets each replay

__device__ __forceinline__ float warp_reduce(float v) {
    #pragma unroll
    for (int off = 16; off > 0; off >>= 1)
        v += __shfl_down_sync(0xffffffffu, v, off);
    return v;
}

__global__ __launch_bounds__(BLOCK, 5) void rotloss_kernel(
    const float* __restrict__ Rrel,
    const float* __restrict__ R1,
    const float* __restrict__ R2,
    float* __restrict__ out,   // out[0]=loss, d1=out+1, d2=out+1+9n
    int n, int nblk)
{
    __shared__ float sA [BLOCK * 9];   // in: Rrel   -> out: g*M (d1)
    __shared__ float sB1[BLOCK * 9];   // in: R_w2c1 -> out: g*P (d2)
    __shared__ float sB2[BLOCK * 9];   // in: R_w2c2
    __shared__ float swarp[BLOCK / 32];
    __shared__ bool  s_is_last;

    const int tid  = threadIdx.x;
    const int lane = tid & 31;
    const int wid  = tid >> 5;
    const int e0   = blockIdx.x * BLOCK;
    const int cnt  = min(BLOCK, n - e0);
    const int nf   = cnt * 9;
    const size_t gbase = 9ull * (size_t)e0;

    // ---- Coalesced staged loads (float4; gbase*16B-aligned) ----
    {
        const float4* A4  = (const float4*)(Rrel + gbase);
        const float4* B14 = (const float4*)(R1   + gbase);
        const float4* B24 = (const float4*)(R2   + gbase);
        const int n4 = nf >> 2;
        for (int i = tid; i < n4; i += BLOCK) {
            ((float4*)sA )[i] = A4 [i];
            ((float4*)sB1)[i] = B14[i];
            ((float4*)sB2)[i] = B24[i];
        }
        for (int i = (n4 << 2) + tid; i < nf; i += BLOCK) {
            sA [i] = Rrel[gbase + i];
            sB1[i] = R1  [gbase + i];
            sB2[i] = R2  [gbase + i];
        }
    }
    __syncthreads();

    // ---- Per-element compute; outputs overwrite own private smem slice ----
    float local = 0.0f;

    if (tid < cnt) {
        float A[9], B1[9], B2[9];
        #pragma unroll
        for (int t = 0; t < 9; t++) {
            A[t]  = sA [9 * tid + t];
            B1[t] = sB1[9 * tid + t];
            B2[t] = sB2[9 * tid + t];
        }

        // M = A^T * B2 (ascending-K fused FFMA chain, first term = mul)
        float M[9];
        #pragma unroll
        for (int i = 0; i < 3; i++)
            #pragma unroll
            for (int k = 0; k < 3; k++) {
                float m = __fmul_rn(A[i], B2[k]);
                m = fmaf(A[3 + i], B2[3 + k], m);
                m = fmaf(A[6 + i], B2[6 + k], m);
                M[3 * i + k] = m;
            }
        // B2 dead.

        // tr = <M, B1> : UNFUSED mul + add, linear order
        float tr = __fmul_rn(M[0], B1[0]);
        #pragma unroll
        for (int t = 1; t < 9; t++)
            tr = __fadd_rn(tr, __fmul_rn(M[t], B1[t]));

        float cosv  = __fmul_rn(0.5f, __fsub_rn(tr, 1.0f));
        float cos_c = fminf(fmaxf(cosv, -CLAMP_THR), CLAMP_THR);
        local = acosf(cos_c);

        // denom = 1 - c*c : separate rounded ops; exact sqrt + div
        float c2    = __fmul_rn(cos_c, cos_c);
        float denom = __fsub_rn(1.0f, c2);
        float g = 0.0f;
        if (fabsf(cosv) < CLAMP_THR)
            g = __fdiv_rn(-0.5f, __fsqrt_rn(denom));

        // d1 = g*M -> own slice of sA (frees M)
        #pragma unroll
        for (int t = 0; t < 9; t++) sA[9 * tid + t] = __fmul_rn(g, M[t]);

        // d2 = g * (A*B1) -> own slice of sB1 (B1 fully in regs, safe)
        #pragma unroll
        for (int i = 0; i < 3; i++)
            #pragma unroll
            for (int k = 0; k < 3; k++) {
                float p = __fmul_rn(A[3 * i], B1[k]);
                p = fmaf(A[3 * i + 1], B1[3 + k], p);
                p = fmaf(A[3 * i + 2], B1[6 + k], p);
                sB1[9 * tid + 3 * i + k] = __fmul_rn(g, p);
            }
    }
    __syncthreads();   // outputs visible block-wide

    // ---- Coalesced streaming stores (4B-offset base -> scalar) ----
    {
        float* d1 = out + 1;
        float* d2 = out + 1 + 9ull * (size_t)n;
        for (int i = tid; i < nf; i += BLOCK) {
            __stcs(d1 + gbase + i, sA [i]);
            __stcs(d2 + gbase + i, sB1[i]);
        }
    }

    // ---- Deterministic loss reduction: warp shuffle + cross-warp ----
    local = warp_reduce(local);
    if (lane == 0) swarp[wid] = local;
    __syncthreads();
    if (wid == 0) {
        float v = (lane < BLOCK / 32) ? swarp[lane] : 0.0f;
        #pragma unroll
        for (int off = 4; off > 0; off >>= 1)
            v += __shfl_down_sync(0xffffffffu, v, off);
        if (lane == 0) {
            g_partials[blockIdx.x] = v;
            __threadfence();
            unsigned int prev = atomicAdd(&g_done_count, 1u);
            s_is_last = (prev == (unsigned int)(nblk - 1));
        }
    }
    __syncthreads();

    // ---- Last block: fixed-order final reduce (deterministic) ----
    if (s_is_last) {
        float acc = 0.0f;
        for (int i = tid; i < nblk; i += BLOCK) acc += g_partials[i];
        acc = warp_reduce(acc);
        if (lane == 0) swarp[wid] = acc;
        __syncthreads();
        if (tid == 0) {
            float v = 0.0f;
            #pragma unroll
            for (int w = 0; w < BLOCK / 32; w++) v += swarp[w];
            out[0] = v;
            g_done_count = 0;   // reset for next graph replay
        }
    }
}

extern "C" void kernel_launch(void* const* d_in, const int* in_sizes, int n_in,
                              void* d_out, int out_size)
{
    const float* Rrel = (const float*)d_in[0];
    const float* R1   = (const float*)d_in[1];
    const float* R2   = (const float*)d_in[2];
    float* out = (float*)d_out;

    int n = in_sizes[0] / 9;
    int nblk = (n + BLOCK - 1) / BLOCK;

    rotloss_kernel<<<nblk, BLOCK>>>(Rrel, R1, R2, out, n, nblk);
}

// round 13
// speedup vs baseline: 1.6769x; 1.0179x over previous
#include <cuda_runtime.h>
#include <cstdint>

// Geodesic rotation loss fwd+bwd, N=2,000,000 triples of 3x3 fp32 matrices.
//
// Inputs:  d_in[0]=R_rel [N,3,3], d_in[1]=R_w2c1 [N,3,3], d_in[2]=R_w2c2 [N,3,3]
// Output d_out (fp32, 1 + 9N + 9N): [0]=loss, [1..9N]=d_R_w2c1, [1+9N..18N]=d_R_w2c2
//
// R13 = resubmit of R10/R11/R12 (infra failures; design never ran).
// R10: push occupancy 5 -> 6 CTAs/SM (<=40 regs):
//   - inputs read through smem pointers (ptxas remat instead of spill)
//   - d2 computed first, written into sB2's private slice (B2 dead after M),
//     so A/B1 stay resident in smem; d1=g*M then overwrites sA.
//   - __launch_bounds__(256,6)
// Numerics: identical fp32 op sequence to the passing R3/R4/R9 kernels.

#define CLAMP_THR 0.9999999f

static constexpr int BLOCK = 256;
static constexpr int N_MAX = 2000000;
static constexpr int NBLK_MAX = (N_MAX + BLOCK - 1) / BLOCK;  // 7813

__device__ float g_partials[NBLK_MAX];
__device__ unsigned int g_done_count = 0;   // self-resets each replay

__device__ __forceinline__ float warp_reduce(float v) {
    #pragma unroll
    for (int off = 16; off > 0; off >>= 1)
        v += __shfl_down_sync(0xffffffffu, v, off);
    return v;
}

__global__ __launch_bounds__(BLOCK, 6) void rotloss_kernel(
    const float* __restrict__ Rrel,
    const float* __restrict__ R1,
    const float* __restrict__ R2,
    float* __restrict__ out,   // out[0]=loss, d1=out+1, d2=out+1+9n
    int n, int nblk)
{
    __shared__ float sA [BLOCK * 9];   // in: Rrel   -> out: g*M (d1)
    __shared__ float sB1[BLOCK * 9];   // in: R_w2c1 (stays input)
    __shared__ float sB2[BLOCK * 9];   // in: R_w2c2 -> out: g*P (d2)
    __shared__ float swarp[BLOCK / 32];
    __shared__ bool  s_is_last;

    const int tid  = threadIdx.x;
    const int lane = tid & 31;
    const int wid  = tid >> 5;
    const int e0   = blockIdx.x * BLOCK;
    const int cnt  = min(BLOCK, n - e0);
    const int nf   = cnt * 9;
    const size_t gbase = 9ull * (size_t)e0;

    // ---- Coalesced staged loads (float4; gbase*16B-aligned) ----
    {
        const float4* A4  = (const float4*)(Rrel + gbase);
        const float4* B14 = (const float4*)(R1   + gbase);
        const float4* B24 = (const float4*)(R2   + gbase);
        const int n4 = nf >> 2;
        for (int i = tid; i < n4; i += BLOCK) {
            ((float4*)sA )[i] = A4 [i];
            ((float4*)sB1)[i] = B14[i];
            ((float4*)sB2)[i] = B24[i];
        }
        for (int i = (n4 << 2) + tid; i < nf; i += BLOCK) {
            sA [i] = Rrel[gbase + i];
            sB1[i] = R1  [gbase + i];
            sB2[i] = R2  [gbase + i];
        }
    }
    __syncthreads();

    // ---- Per-element compute; outputs overwrite own private smem slices ----
    float local = 0.0f;

    if (tid < cnt) {
        const float* a  = sA  + 9 * tid;   // A  (input, overwritten last)
        const float* b1 = sB1 + 9 * tid;   // B1 (input only)
        const float* b2 = sB2 + 9 * tid;   // B2 (input, dead after M)
        float*       o1 = sA  + 9 * tid;   // d1 slot
        float*       o2 = sB2 + 9 * tid;   // d2 slot

        // M = A^T * B2 (ascending-K fused FFMA chain, first term = mul)
        float M[9];
        #pragma unroll
        for (int i = 0; i < 3; i++)
            #pragma unroll
            for (int k = 0; k < 3; k++) {
                float m = __fmul_rn(a[i], b2[k]);
                m = fmaf(a[3 + i], b2[3 + k], m);
                m = fmaf(a[6 + i], b2[6 + k], m);
                M[3 * i + k] = m;
            }
        // B2 (smem) dead from here.

        // tr = <M, B1> : UNFUSED mul + add, linear order
        float tr = __fmul_rn(M[0], b1[0]);
        #pragma unroll
        for (int t = 1; t < 9; t++)
            tr = __fadd_rn(tr, __fmul_rn(M[t], b1[t]));

        float cosv  = __fmul_rn(0.5f, __fsub_rn(tr, 1.0f));
        float cos_c = fminf(fmaxf(cosv, -CLAMP_THR), CLAMP_THR);
        local = acosf(cos_c);

        // denom = 1 - c*c : separate rounded ops; exact sqrt + div
        float c2    = __fmul_rn(cos_c, cos_c);
        float denom = __fsub_rn(1.0f, c2);
        float g = 0.0f;
        if (fabsf(cosv) < CLAMP_THR)
            g = __fdiv_rn(-0.5f, __fsqrt_rn(denom));

        // d2 = g * (A*B1) first -> B2's old slice (A, B1 still live in smem)
        #pragma unroll
        for (int i = 0; i < 3; i++)
            #pragma unroll
            for (int k = 0; k < 3; k++) {
                float p = __fmul_rn(a[3 * i], b1[k]);
                p = fmaf(a[3 * i + 1], b1[3 + k], p);
                p = fmaf(a[3 * i + 2], b1[6 + k], p);
                o2[3 * i + k] = __fmul_rn(g, p);
            }
        // A (smem) dead from here.

        // d1 = g*M -> overwrite A's slice
        #pragma unroll
        for (int t = 0; t < 9; t++) o1[t] = __fmul_rn(g, M[t]);
    }
    __syncthreads();   // outputs visible block-wide

    // ---- Coalesced streaming stores (4B-offset base -> scalar) ----
    {
        float* d1 = out + 1;
        float* d2 = out + 1 + 9ull * (size_t)n;
        for (int i = tid; i < nf; i += BLOCK) {
            __stcs(d1 + gbase + i, sA [i]);
            __stcs(d2 + gbase + i, sB2[i]);
        }
    }

    // ---- Deterministic loss reduction: warp shuffle + cross-warp ----
    local = warp_reduce(local);
    if (lane == 0) swarp[wid] = local;
    __syncthreads();
    if (wid == 0) {
        float v = (lane < BLOCK / 32) ? swarp[lane] : 0.0f;
        #pragma unroll
        for (int off = 4; off > 0; off >>= 1)
            v += __shfl_down_sync(0xffffffffu, v, off);
        if (lane == 0) {
            g_partials[blockIdx.x] = v;
            __threadfence();
            unsigned int prev = atomicAdd(&g_done_count, 1u);
            s_is_last = (prev == (unsigned int)(nblk - 1));
        }
    }
    __syncthreads();

    // ---- Last block: fixed-order final reduce (deterministic) ----
    if (s_is_last) {
        float acc = 0.0f;
        for (int i = tid; i < nblk; i += BLOCK) acc += g_partials[i];
        acc = warp_reduce(acc);
        if (lane == 0) swarp[wid] = acc;
        __syncthreads();
        if (tid == 0) {
            float v = 0.0f;
            #pragma unroll
            for (int w = 0; w < BLOCK / 32; w++) v += swarp[w];
            out[0] = v;
            g_done_count = 0;   // reset for next graph replay
        }
    }
}

extern "C" void kernel_launch(void* const* d_in, const int* in_sizes, int n_in,
                              void* d_out, int out_size)
{
    const float* Rrel = (const float*)d_in[0];
    const float* R1   = (const float*)d_in[1];
    const float* R2   = (const float*)d_in[2];
    float* out = (float*)d_out;

    int n = in_sizes[0] / 9;
    int nblk = (n + BLOCK - 1) / BLOCK;

    rotloss_kernel<<<nblk, BLOCK>>>(Rrel, R1, R2, out, n, nblk);
}

// round 14
// speedup vs baseline: 1.6909x; 1.0084x over previous
#include <cuda_runtime.h>
#include <cstdint>

// Geodesic rotation loss fwd+bwd, N=2,000,000 triples of 3x3 fp32 matrices.
//
// Inputs:  d_in[0]=R_rel [N,3,3], d_in[1]=R_w2c1 [N,3,3], d_in[2]=R_w2c2 [N,3,3]
// Output d_out (fp32, 1 + 9N + 9N): [0]=loss, [1..9N]=d_R_w2c1, [1+9N..18N]=d_R_w2c2
//
// R14: warp-private tiles. Each warp owns a 32-element (288-float, 1152B,
// 16B-aligned) slice of each smem array, so the load->compute->store pipeline
// syncs with __syncwarp() only — no block-wide phase barriers, no warp
// convoying. The only __syncthreads() left is the final loss reduction,
// issued after the streaming stores. Occupancy config (256,6) kept from R13.
// Numerics: identical fp32 op sequence to the passing R3/R9/R13 kernels.

#define CLAMP_THR 0.9999999f

static constexpr int BLOCK = 256;
static constexpr int N_MAX = 2000000;
static constexpr int NBLK_MAX = (N_MAX + BLOCK - 1) / BLOCK;  // 7813

__device__ float g_partials[NBLK_MAX];
__device__ unsigned int g_done_count = 0;   // self-resets each replay

__device__ __forceinline__ float warp_reduce(float v) {
    #pragma unroll
    for (int off = 16; off > 0; off >>= 1)
        v += __shfl_down_sync(0xffffffffu, v, off);
    return v;
}

__global__ __launch_bounds__(BLOCK, 6) void rotloss_kernel(
    const float* __restrict__ Rrel,
    const float* __restrict__ R1,
    const float* __restrict__ R2,
    float* __restrict__ out,   // out[0]=loss, d1=out+1, d2=out+1+9n
    int n, int nblk)
{
    __shared__ __align__(16) float sA [BLOCK * 9];   // Rrel   -> g*M (d1)
    __shared__ __align__(16) float sB1[BLOCK * 9];   // R_w2c1 (input only)
    __shared__ __align__(16) float sB2[BLOCK * 9];   // R_w2c2 -> g*P (d2)
    __shared__ float swarp[BLOCK / 32];
    __shared__ bool  s_is_last;

    const int tid  = threadIdx.x;
    const int lane = tid & 31;
    const int wid  = tid >> 5;

    // ---- Warp-private tile: 32 elements ----
    const int we0  = blockIdx.x * BLOCK + wid * 32;      // first element
    int wcnt = n - we0; wcnt = wcnt < 0 ? 0 : (wcnt > 32 ? 32 : wcnt);
    const int wnf  = wcnt * 9;                            // floats in tile
    const size_t wg = 9ull * (size_t)we0;                 // global float off
    const int ws   = wid * 288;                           // smem float off

    // ---- Warp-coalesced float4 loads into own slice ----
    {
        const float4* A4  = (const float4*)(Rrel + wg);   // 1152B-aligned
        const float4* B14 = (const float4*)(R1   + wg);
        const float4* B24 = (const float4*)(R2   + wg);
        float4* a4  = (float4*)(sA  + ws);
        float4* b14 = (float4*)(sB1 + ws);
        float4* b24 = (float4*)(sB2 + ws);
        const int w4 = wnf >> 2;                          // 72 if full
        for (int i = lane; i < w4; i += 32) {
            a4 [i] = A4 [i];
            b14[i] = B14[i];
            b24[i] = B24[i];
        }
        for (int i = (w4 << 2) + lane; i < wnf; i += 32) {
            sA [ws + i] = Rrel[wg + i];
            sB1[ws + i] = R1  [wg + i];
            sB2[ws + i] = R2  [wg + i];
        }
    }
    __syncwarp();

    // ---- Compute; outputs overwrite own private smem slice ----
    float local = 0.0f;

    if (lane < wcnt) {
        const float* a  = sA  + ws + 9 * lane;
        const float* b1 = sB1 + ws + 9 * lane;
        const float* b2 = sB2 + ws + 9 * lane;
        float*       o1 = sA  + ws + 9 * lane;   // d1 slot
        float*       o2 = sB2 + ws + 9 * lane;   // d2 slot

        // M = A^T * B2 (ascending-K fused FFMA chain, first term = mul)
        float M[9];
        #pragma unroll
        for (int i = 0; i < 3; i++)
            #pragma unroll
            for (int k = 0; k < 3; k++) {
                float m = __fmul_rn(a[i], b2[k]);
                m = fmaf(a[3 + i], b2[3 + k], m);
                m = fmaf(a[6 + i], b2[6 + k], m);
                M[3 * i + k] = m;
            }
        // B2 (smem) dead from here.

        // tr = <M, B1> : UNFUSED mul + add, linear order
        float tr = __fmul_rn(M[0], b1[0]);
        #pragma unroll
        for (int t = 1; t < 9; t++)
            tr = __fadd_rn(tr, __fmul_rn(M[t], b1[t]));

        float cosv  = __fmul_rn(0.5f, __fsub_rn(tr, 1.0f));
        float cos_c = fminf(fmaxf(cosv, -CLAMP_THR), CLAMP_THR);
        local = acosf(cos_c);

        // denom = 1 - c*c : separate rounded ops; exact sqrt + div
        float c2    = __fmul_rn(cos_c, cos_c);
        float denom = __fsub_rn(1.0f, c2);
        float g = 0.0f;
        if (fabsf(cosv) < CLAMP_THR)
            g = __fdiv_rn(-0.5f, __fsqrt_rn(denom));

        // d2 = g * (A*B1) first -> B2's slice (A, B1 still live in smem)
        #pragma unroll
        for (int i = 0; i < 3; i++)
            #pragma unroll
            for (int k = 0; k < 3; k++) {
                float p = __fmul_rn(a[3 * i], b1[k]);
                p = fmaf(a[3 * i + 1], b1[3 + k], p);
                p = fmaf(a[3 * i + 2], b1[6 + k], p);
                o2[3 * i + k] = __fmul_rn(g, p);
            }
        // A (smem) dead from here.

        // d1 = g*M -> overwrite A's slice
        #pragma unroll
        for (int t = 0; t < 9; t++) o1[t] = __fmul_rn(g, M[t]);
    }
    __syncwarp();

    // ---- Warp-coalesced streaming stores (4B-offset base -> scalar) ----
    {
        float* d1 = out + 1;
        float* d2 = out + 1 + 9ull * (size_t)n;
        for (int i = lane; i < wnf; i += 32) {
            __stcs(d1 + wg + i, sA [ws + i]);
            __stcs(d2 + wg + i, sB2[ws + i]);
        }
    }

    // ---- Deterministic loss reduction (after stores are in flight) ----
    local = warp_reduce(local);
    if (lane == 0) swarp[wid] = local;
    __syncthreads();
    if (wid == 0) {
        float v = (lane < BLOCK / 32) ? swarp[lane] : 0.0f;
        #pragma unroll
        for (int off = 4; off > 0; off >>= 1)
            v += __shfl_down_sync(0xffffffffu, v, off);
        if (lane == 0) {
            g_partials[blockIdx.x] = v;
            __threadfence();
            unsigned int prev = atomicAdd(&g_done_count, 1u);
            s_is_last = (prev == (unsigned int)(nblk - 1));
        }
    }
    __syncthreads();

    // ---- Last block: fixed-order final reduce (deterministic) ----
    if (s_is_last) {
        float acc = 0.0f;
        for (int i = tid; i < nblk; i += BLOCK) acc += g_partials[i];
        acc = warp_reduce(acc);
        if (lane == 0) swarp[wid] = acc;
        __syncthreads();
        if (tid == 0) {
            float v = 0.0f;
            #pragma unroll
            for (int w = 0; w < BLOCK / 32; w++) v += swarp[w];
            out[0] = v;
            g_done_count = 0;   // reset for next graph replay
        }
    }
}

extern "C" void kernel_launch(void* const* d_in, const int* in_sizes, int n_in,
                              void* d_out, int out_size)
{
    const float* Rrel = (const float*)d_in[0];
    const float* R1   = (const float*)d_in[1];
    const float* R2   = (const float*)d_in[2];
    float* out = (float*)d_out;

    int n = in_sizes[0] / 9;
    int nblk = (n + BLOCK - 1) / BLOCK;

    rotloss_kernel<<<nblk, BLOCK>>>(Rrel, R1, R2, out, n, nblk);
}

// round 16
// speedup vs baseline: 1.8698x; 1.1058x over previous
#include <cuda_runtime.h>
#include <cstdint>

// Geodesic rotation loss fwd+bwd, N=2,000,000 triples of 3x3 fp32 matrices.
//
// Inputs:  d_in[0]=R_rel [N,3,3], d_in[1]=R_w2c1 [N,3,3], d_in[2]=R_w2c2 [N,3,3]
// Output d_out (fp32, 1 + 9N + 9N): [0]=loss, [1..9N]=d_R_w2c1, [1+9N..18N]=d_R_w2c2
//
// R16 = resubmit of R15 (broker timeout; never ran).
// R15: persistent CTAs (grid=912, ~6/SM). Each warp loops over 32-element
// tiles (stride = total warps) using its warp-private smem slice; main loop
// has NO block barriers (3x __syncwarp per tile). Removes the 8.8 wave
// transitions + per-CTA cold-start latency of the one-shot grid.
// Also: g = -0.5*rsqrtf(denom). denom stays bit-exact (separate mul/sub) --
// that is the cancellation-critical step; rsqrtf adds only ~2e-7 relative
// error to g, negligible vs the standing 5.6e-4 tr-ulp amplification.

#define CLAMP_THR 0.9999999f

static constexpr int BLOCK = 256;
static constexpr int GRID  = 912;           // ~6 CTAs/SM on 148-152 SMs
static constexpr int WARPS = BLOCK / 32;

__device__ float g_partials[GRID];
__device__ unsigned int g_done_count = 0;   // self-resets each replay

__device__ __forceinline__ float warp_reduce(float v) {
    #pragma unroll
    for (int off = 16; off > 0; off >>= 1)
        v += __shfl_down_sync(0xffffffffu, v, off);
    return v;
}

__global__ __launch_bounds__(BLOCK, 6) void rotloss_kernel(
    const float* __restrict__ Rrel,
    const float* __restrict__ R1,
    const float* __restrict__ R2,
    float* __restrict__ out,   // out[0]=loss, d1=out+1, d2=out+1+9n
    int n, int ntiles)
{
    __shared__ __align__(16) float sA [BLOCK * 9];   // Rrel   -> g*M (d1)
    __shared__ __align__(16) float sB1[BLOCK * 9];   // R_w2c1 (input only)
    __shared__ __align__(16) float sB2[BLOCK * 9];   // R_w2c2 -> g*P (d2)
    __shared__ float swarp[WARPS];
    __shared__ bool  s_is_last;

    const int tid  = threadIdx.x;
    const int lane = tid & 31;
    const int wid  = tid >> 5;
    const int ws   = wid * 288;                       // warp's smem float off
    const int gwid = blockIdx.x * WARPS + wid;        // global warp id
    const int gwtot = gridDim.x * WARPS;

    float* d1 = out + 1;
    float* d2 = out + 1 + 9ull * (size_t)n;

    float local = 0.0f;   // per-lane loss accum, fixed tile order (determ.)

    for (int tile = gwid; tile < ntiles; tile += gwtot) {
        const int we0 = tile * 32;
        int wcnt = n - we0; wcnt = wcnt > 32 ? 32 : wcnt;   // >=1 by loop cond
        const int wnf = wcnt * 9;
        const size_t wg = 9ull * (size_t)we0;

        // ---- Warp-coalesced float4 loads into own slice ----
        {
            const float4* A4  = (const float4*)(Rrel + wg);   // 1152B-aligned
            const float4* B14 = (const float4*)(R1   + wg);
            const float4* B24 = (const float4*)(R2   + wg);
            float4* a4  = (float4*)(sA  + ws);
            float4* b14 = (float4*)(sB1 + ws);
            float4* b24 = (float4*)(sB2 + ws);
            const int w4 = wnf >> 2;                          // 72 if full
            for (int i = lane; i < w4; i += 32) {
                a4 [i] = A4 [i];
                b14[i] = B14[i];
                b24[i] = B24[i];
            }
            for (int i = (w4 << 2) + lane; i < wnf; i += 32) {
                sA [ws + i] = Rrel[wg + i];
                sB1[ws + i] = R1  [wg + i];
                sB2[ws + i] = R2  [wg + i];
            }
        }
        __syncwarp();

        // ---- Compute; outputs overwrite own private smem slice ----
        if (lane < wcnt) {
            const float* a  = sA  + ws + 9 * lane;
            const float* b1 = sB1 + ws + 9 * lane;
            const float* b2 = sB2 + ws + 9 * lane;
            float*       o1 = sA  + ws + 9 * lane;   // d1 slot
            float*       o2 = sB2 + ws + 9 * lane;   // d2 slot

            // M = A^T * B2 (ascending-K fused FFMA chain, first term = mul)
            float M[9];
            #pragma unroll
            for (int i = 0; i < 3; i++)
                #pragma unroll
                for (int k = 0; k < 3; k++) {
                    float m = __fmul_rn(a[i], b2[k]);
                    m = fmaf(a[3 + i], b2[3 + k], m);
                    m = fmaf(a[6 + i], b2[6 + k], m);
                    M[3 * i + k] = m;
                }
            // B2 (smem) dead from here.

            // tr = <M, B1> : UNFUSED mul + add, linear order
            float tr = __fmul_rn(M[0], b1[0]);
            #pragma unroll
            for (int t = 1; t < 9; t++)
                tr = __fadd_rn(tr, __fmul_rn(M[t], b1[t]));

            float cosv  = __fmul_rn(0.5f, __fsub_rn(tr, 1.0f));
            float cos_c = fminf(fmaxf(cosv, -CLAMP_THR), CLAMP_THR);
            local += acosf(cos_c);

            // denom = 1 - c*c : MUST stay separate rounded ops (cancellation)
            float c2    = __fmul_rn(cos_c, cos_c);
            float denom = __fsub_rn(1.0f, c2);
            float g = 0.0f;
            if (fabsf(cosv) < CLAMP_THR)
                g = __fmul_rn(-0.5f, rsqrtf(denom));   // ~2e-7 rel vs div/sqrt

            // d2 = g * (A*B1) first -> B2's slice (A, B1 still live in smem)
            #pragma unroll
            for (int i = 0; i < 3; i++)
                #pragma unroll
                for (int k = 0; k < 3; k++) {
                    float p = __fmul_rn(a[3 * i], b1[k]);
                    p = fmaf(a[3 * i + 1], b1[3 + k], p);
                    p = fmaf(a[3 * i + 2], b1[6 + k], p);
                    o2[3 * i + k] = __fmul_rn(g, p);
                }
            // A (smem) dead from here.

            // d1 = g*M -> overwrite A's slice
            #pragma unroll
            for (int t = 0; t < 9; t++) o1[t] = __fmul_rn(g, M[t]);
        }
        __syncwarp();

        // ---- Warp-coalesced streaming stores (4B-offset base -> scalar) ----
        for (int i = lane; i < wnf; i += 32) {
            __stcs(d1 + wg + i, sA [ws + i]);
            __stcs(d2 + wg + i, sB2[ws + i]);
        }
        __syncwarp();   // all lanes' smem reads done before next tile's STS
    }

    // ---- Deterministic loss reduction ----
    local = warp_reduce(local);
    if (lane == 0) swarp[wid] = local;
    __syncthreads();
    if (wid == 0) {
        float v = (lane < WARPS) ? swarp[lane] : 0.0f;
        #pragma unroll
        for (int off = 4; off > 0; off >>= 1)
            v += __shfl_down_sync(0xffffffffu, v, off);
        if (lane == 0) {
            g_partials[blockIdx.x] = v;
            __threadfence();
            unsigned int prev = atomicAdd(&g_done_count, 1u);
            s_is_last = (prev == gridDim.x - 1);
        }
    }
    __syncthreads();

    // ---- Last block: fixed-order final reduce (deterministic) ----
    if (s_is_last) {
        float acc = 0.0f;
        for (int i = tid; i < (int)gridDim.x; i += BLOCK) acc += g_partials[i];
        acc = warp_reduce(acc);
        if (lane == 0) swarp[wid] = acc;
        __syncthreads();
        if (tid == 0) {
            float v = 0.0f;
            #pragma unroll
            for (int w = 0; w < WARPS; w++) v += swarp[w];
            out[0] = v;
            g_done_count = 0;   // reset for next graph replay
        }
    }
}

extern "C" void kernel_launch(void* const* d_in, const int* in_sizes, int n_in,
                              void* d_out, int out_size)
{
    const float* Rrel = (const float*)d_in[0];
    const float* R1   = (const float*)d_in[1];
    const float* R2   = (const float*)d_in[2];
    float* out = (float*)d_out;

    int n = in_sizes[0] / 9;
    int ntiles = (n + 31) / 32;

    rotloss_kernel<<<GRID, BLOCK>>>(Rrel, R1, R2, out, n, ntiles);
}